// round 14
// baseline (speedup 1.0000x reference)
#include <cuda_runtime.h>
#include <math.h>

// Inputs (metadata order):
//   d_in[0]: z          float32, n_nodes*512   (n_nodes = 50000)
//   d_in[1]: edge_index int32,   2*n_edges     (n_edges = 150000)
// Output: float32, 150000

#define D 512
#define ROW_U4 (D / 16)        // 32 uint4 per int8 row (512 bytes)
#define MAX_NODES 50000
#define EPS 1e-6f

#define WPB 6                   // warps per block (edge kernel)
#define STAGES 3                // pipeline ring depth

// Scratch: quantized normalized rows (25.6 MB) + per-node {scale, sum} pairs.
__device__ uint4  g_q[(size_t)MAX_NODES * ROW_U4];
__device__ float2 g_ss[MAX_NODES];   // x = quant step of normalized row, y = sum of normalized elems

__device__ __forceinline__ unsigned pack4(float x, float y, float z, float w, float k) {
    int q0 = __float2int_rn(x * k);
    int q1 = __float2int_rn(y * k);
    int q2 = __float2int_rn(z * k);
    int q3 = __float2int_rn(w * k);
    q0 = max(-127, min(127, q0));
    q1 = max(-127, min(127, q1));
    q2 = max(-127, min(127, q2));
    q3 = max(-127, min(127, q3));
    return (unsigned)(q0 & 0xFF) | ((unsigned)(q1 & 0xFF) << 8) |
           ((unsigned)(q2 & 0xFF) << 16) | ((unsigned)(q3 & 0xFF) << 24);
}

__device__ __forceinline__ void cp_async16(void* smem_dst, const void* gsrc) {
    unsigned saddr = (unsigned)__cvta_generic_to_shared(smem_dst);
    asm volatile("cp.async.cg.shared.global [%0], [%1], 16;\n" :: "r"(saddr), "l"(gsrc));
}

// ---------------------------------------------------------------------------
// Kernel 1: one warp per node row. Streaming (__ldcs) reads of z so the 102MB
// stream does not evict the freshly written 25.6MB table from L2.
// ---------------------------------------------------------------------------
__global__ void normalize_kernel(const float* __restrict__ z, int n_nodes) {
    int row  = (blockIdx.x * blockDim.x + threadIdx.x) >> 5;
    int lane = threadIdx.x & 31;
    if (row >= n_nodes) return;

    const float4* __restrict__ Z = (const float4*)(z + (size_t)row * D);
    float4 v[4];
    float n2 = 0.f, s = 0.f, mx = 0.f;
#pragma unroll
    for (int j = 0; j < 4; j++) {
        v[j] = __ldcs(Z + lane + 32 * j);   // evict-first
        n2 += v[j].x * v[j].x + v[j].y * v[j].y + v[j].z * v[j].z + v[j].w * v[j].w;
        s  += v[j].x + v[j].y + v[j].z + v[j].w;
        mx = fmaxf(mx, fmaxf(fmaxf(fabsf(v[j].x), fabsf(v[j].y)),
                             fmaxf(fabsf(v[j].z), fabsf(v[j].w))));
    }
#pragma unroll
    for (int off = 16; off > 0; off >>= 1) {
        n2 += __shfl_xor_sync(0xFFFFFFFFu, n2, off);
        s  += __shfl_xor_sync(0xFFFFFFFFu, s,  off);
        mx = fmaxf(mx, __shfl_xor_sync(0xFFFFFFFFu, mx, off));
    }

    float inv = rsqrtf(n2);
    float step = mx * inv * (1.0f / 127.0f);   // quant step of normalized row
    float qk = 127.0f / mx;                    // v_raw * qk == v_norm / step

    if (lane == 0) g_ss[row] = make_float2(step, s * inv);

    uint4 u;
    u.x = pack4(v[0].x, v[0].y, v[0].z, v[0].w, qk);
    u.y = pack4(v[1].x, v[1].y, v[1].z, v[1].w, qk);
    u.z = pack4(v[2].x, v[2].y, v[2].z, v[2].w, qk);
    u.w = pack4(v[3].x, v[3].y, v[3].z, v[3].w, qk);
    g_q[(size_t)row * ROW_U4 + lane] = u;  // coalesced; table stays L2-resident
}

// ---------------------------------------------------------------------------
// Kernel 2: persistent warps, 8 lanes/edge, 4 edges per warp-batch,
// 3-stage cp.async ring with 2 groups in flight (wait_group 2):
//   compute b  |  rows b+W, b+2W in flight  |  idx b+3W prefetching
// SMEM: 6 warps x 3 stages x 4KB = 72KB/block -> 3 blocks/SM (18 warps/SM).
// ---------------------------------------------------------------------------
__global__ void __launch_bounds__(WPB * 32)
edge_kernel(const int* __restrict__ ei,
            float* __restrict__ out,
            int n_edges) {
    __shared__ __align__(16) unsigned char sbuf[WPB][STAGES][4096];

    int wib  = threadIdx.x >> 5;
    int lane = threadIdx.x & 31;
    int sub  = lane >> 3;      // edge within batch (0..3)
    int sl   = lane & 7;       // lane within 8-lane edge group

    int nb = (n_edges + 3) >> 2;              // number of 4-edge batches
    int W  = gridDim.x * WPB;                 // total warps
    int w0 = blockIdx.x * WPB + wib;
    if (w0 >= nb) return;

    // --- helpers (inlined) ---------------------------------------------------
    // issue: 8 cp.async16 per lane staging rows (ia, ib) of one edge.
    // loadidx: indices for batch b's edge `sub` (clamped).

    // --- prologue -------------------------------------------------------------
    int ia0, ib0;
    {
        int e = w0 * 4 + sub; int ec = min(e, n_edges - 1);
        ia0 = __ldg(ei + ec); ib0 = __ldg(ei + n_edges + ec);
    }
    {
        unsigned char* ebuf = &sbuf[wib][0][sub * 1024];
        const uint4* A = g_q + (size_t)ia0 * ROW_U4;
        const uint4* B = g_q + (size_t)ib0 * ROW_U4;
#pragma unroll
        for (int j = 0; j < 4; j++) {
            cp_async16(ebuf + 16 * (sl + 8 * j),       &A[sl + 8 * j]);
            cp_async16(ebuf + 512 + 16 * (sl + 8 * j), &B[sl + 8 * j]);
        }
    }
    asm volatile("cp.async.commit_group;\n" ::: "memory");
    float2 ssa_c = g_ss[ia0], ssb_c = g_ss[ib0];

    int ia1 = ia0, ib1 = ib0;
    bool h1 = (w0 + W) < nb;
    if (h1) {
        int e = (w0 + W) * 4 + sub; int ec = min(e, n_edges - 1);
        ia1 = __ldg(ei + ec); ib1 = __ldg(ei + n_edges + ec);
        unsigned char* ebuf = &sbuf[wib][1][sub * 1024];
        const uint4* A = g_q + (size_t)ia1 * ROW_U4;
        const uint4* B = g_q + (size_t)ib1 * ROW_U4;
#pragma unroll
        for (int j = 0; j < 4; j++) {
            cp_async16(ebuf + 16 * (sl + 8 * j),       &A[sl + 8 * j]);
            cp_async16(ebuf + 512 + 16 * (sl + 8 * j), &B[sl + 8 * j]);
        }
    }
    asm volatile("cp.async.commit_group;\n" ::: "memory");
    float2 ssa_1 = ssa_c, ssb_1 = ssb_c;
    if (h1) { ssa_1 = g_ss[ia1]; ssb_1 = g_ss[ib1]; }

    // idx for b+2W (used by first loop iteration's issue)
    int iai = ia0, ibi = ib0;
    if ((w0 + 2 * W) < nb) {
        int e = (w0 + 2 * W) * 4 + sub; int ec = min(e, n_edges - 1);
        iai = __ldg(ei + ec); ibi = __ldg(ei + n_edges + ec);
    }

    int stage = 0;
    for (int b = w0; b < nb; b += W) {
        bool has2 = (b + 2 * W) < nb;

        // issue rows for batch b+2W into stage (stage+2)%3
        if (has2) {
            int st2 = stage + 2; if (st2 >= STAGES) st2 -= STAGES;
            unsigned char* ebuf = &sbuf[wib][st2][sub * 1024];
            const uint4* A = g_q + (size_t)iai * ROW_U4;
            const uint4* B = g_q + (size_t)ibi * ROW_U4;
#pragma unroll
            for (int j = 0; j < 4; j++) {
                cp_async16(ebuf + 16 * (sl + 8 * j),       &A[sl + 8 * j]);
                cp_async16(ebuf + 512 + 16 * (sl + 8 * j), &B[sl + 8 * j]);
            }
        }
        asm volatile("cp.async.commit_group;\n" ::: "memory");  // one group per iter (possibly empty)

        // scalars for b+2W (latency hidden behind wait + compute)
        float2 ssa_2 = ssa_1, ssb_2 = ssb_1;
        if (has2) { ssa_2 = g_ss[iai]; ssb_2 = g_ss[ibi]; }

        // prefetch indices for b+3W
        int iap = iai, ibp = ibi;
        if ((b + 3 * W) < nb) {
            int e = (b + 3 * W) * 4 + sub; int ec = min(e, n_edges - 1);
            iap = __ldg(ei + ec); ibp = __ldg(ei + n_edges + ec);
        }

        // rows of batch b are in the 3rd-newest group -> done after this wait
        asm volatile("cp.async.wait_group 2;\n" ::: "memory");

        // compute current batch b
        {
            unsigned char* ebuf = &sbuf[wib][stage][sub * 1024];
            const uint4* sA = (const uint4*)ebuf;
            const uint4* sB = (const uint4*)(ebuf + 512);

            int idot = 0;
#pragma unroll
            for (int j = 0; j < 4; j++) {
                uint4 a  = sA[sl + 8 * j];
                uint4 bq = sB[sl + 8 * j];
                idot = __dp4a((int)a.x, (int)bq.x, idot);
                idot = __dp4a((int)a.y, (int)bq.y, idot);
                idot = __dp4a((int)a.z, (int)bq.z, idot);
                idot = __dp4a((int)a.w, (int)bq.w, idot);
            }

            unsigned gmask = 0xFFu << (sub * 8);
            idot = __reduce_add_sync(gmask, idot);

            int e = b * 4 + sub;
            if (sl == 0 && e < n_edges) {
                float dot = (float)idot * ssa_c.x * ssb_c.x;
                float d2 = 2.0f - 2.0f * dot
                         + 2.0f * EPS * (ssa_c.y - ssb_c.y)
                         + (float)D * EPS * EPS;
                d2 = fmaxf(d2, 0.0f);
                float v = 1.0f - sqrtf(d2);
                out[e] = 1.0f / (1.0f + expf(-v));
            }
        }

        // rotate pipeline state
        ssa_c = ssa_1; ssb_c = ssb_1;
        ssa_1 = ssa_2; ssb_1 = ssb_2;
        iai = iap; ibi = ibp;
        stage = (stage == STAGES - 1) ? 0 : stage + 1;
    }
}

extern "C" void kernel_launch(void* const* d_in, const int* in_sizes, int n_in,
                              void* d_out, int out_size) {
    const float* z = (const float*)d_in[0];
    const int* ei  = (const int*)d_in[1];
    float* out     = (float*)d_out;

    int n_nodes = in_sizes[0] / D;   // 50000
    int n_edges = out_size;          // 150000

    {
        long long tt = (long long)n_nodes * 32;
        int blocks = (int)((tt + 255) / 256);
        normalize_kernel<<<blocks, 256>>>(z, n_nodes);
    }
    {
        int blocks = 148 * 3;   // persistent: 3 blocks/SM (72KB smem each)
        edge_kernel<<<blocks, WPB * 32>>>(ei, out, n_edges);
    }
}